// round 2
// baseline (speedup 1.0000x reference)
#include <cuda_runtime.h>
#include <cstdint>

// ---------------------------------------------------------------------------
// Affine coupling layer, fp32, packed-f32x2 register-tiled GEMM chain.
//
// Per 128-row tile (one block, 256 threads):
//   At[k][m]   : transposed activations in shared (k = input feature, m = row)
//   Wp[n2][k]  : weights in shared, paired over output-n (float2) so the
//                inner loop is pure fma.rn.f32x2
//   res        : compressed-residual accumulator, lives in registers
//   st_s       : s_raw/t staging (stride 129, conflict-free epilogue reads)
// ---------------------------------------------------------------------------

typedef unsigned long long ull;

__device__ __forceinline__ ull pack2(float lo, float hi) {
    ull r;
    asm("mov.b64 %0, {%1, %2};" : "=l"(r) : "f"(lo), "f"(hi));
    return r;
}
__device__ __forceinline__ float2 unpack2(ull v) {
    float2 f;
    asm("mov.b64 {%0, %1}, %2;" : "=f"(f.x), "=f"(f.y) : "l"(v));
    return f;
}
__device__ __forceinline__ ull fma2(ull a, ull b, ull c) {
    ull d;
    asm("fma.rn.f32x2 %0, %1, %2, %3;" : "=l"(d) : "l"(a), "l"(b), "l"(c));
    return d;
}
__device__ __forceinline__ ull add2(ull a, ull b) {
    ull d;
    asm("add.rn.f32x2 %0, %1, %2;" : "=l"(d) : "l"(a), "l"(b));
    return d;
}

// jax.nn.elu, alpha=1:  x>0 ? x : expm1(x).  __expf-1 error is <=1e-7 absolute
// (only taken for x<0), far below the 1e-3 gate.
__device__ __forceinline__ float eluf(float v) {
    return v > 0.0f ? v : (__expf(v) - 1.0f);
}

static constexpr int ROWS_PER_BLOCK = 128;
static constexpr int THREADS = 256;
static constexpr int H = 128;   // hidden
static constexpr int P = 64;    // pass/trans dim

// Shared layout (in floats)
static constexpr int OFF_AT   = 0;                   // 128*128 = 16384
static constexpr int OFF_WP   = 16384;               // 128*128 = 16384
static constexpr int OFF_XS   = 32768;               // 128 rows * 65 float2 = 16640 floats
static constexpr int OFF_BIAS = 32768 + 16640;       // 4*128 = 512
static constexpr int SMEM_FLOATS = OFF_BIAS + 512;   // 49920 floats = 199680 B
// st_s overlays [0, 128*129) = 16512 floats (At + first 128 floats of Wp; both
// dead after the last GEMM).

// Load W (HO=128 rows x K cols, row-major) into paired layout:
//   Wp[(n/2)*K + k] (float2) = { W[n_even][k], W[n_odd][k] }
template <int K>
__device__ __forceinline__ void load_wp(float* __restrict__ Wp,
                                        const float* __restrict__ W, int tid) {
    #pragma unroll 1
    for (int u = tid; u < 128 * K; u += THREADS) {
        int n = u / K;          // K is 64/128 -> shifts
        int k = u - n * K;
        Wp[(((n >> 1) * K + k) << 1) + (n & 1)] = __ldg(&W[u]);
    }
}

// acc[m_local][n_pair] += At[k][m] * W[n][k]  over k
template <int K>
__device__ __forceinline__ void gemm(const float* __restrict__ At,
                                     const float* __restrict__ Wp,
                                     ull acc[4][8], int tx, int wy) {
    #pragma unroll
    for (int i = 0; i < 4; i++)
        #pragma unroll
        for (int jj = 0; jj < 8; jj++) acc[i][jj] = 0ull;

    const float* wbase = Wp + (wy * 8) * K * 2;
    const float* abase = At + tx * 4;

    #pragma unroll 4
    for (int k = 0; k < K; k++) {
        float4 av = *reinterpret_cast<const float4*>(abase + k * 128);
        ull w[8];
        #pragma unroll
        for (int jj = 0; jj < 8; jj++)
            w[jj] = *reinterpret_cast<const ull*>(wbase + (jj * K + k) * 2);
        float a[4] = {av.x, av.y, av.z, av.w};
        #pragma unroll
        for (int i = 0; i < 4; i++) {
            ull ad = pack2(a[i], a[i]);
            #pragma unroll
            for (int jj = 0; jj < 8; jj++)
                acc[i][jj] = fma2(ad, w[jj], acc[i][jj]);
        }
    }
}

__device__ __forceinline__ void apply_bias(ull acc[4][8],
                                           const float* __restrict__ bias_n,
                                           int wy) {
    #pragma unroll
    for (int jj = 0; jj < 8; jj++) {
        ull bp = *reinterpret_cast<const ull*>(bias_n + wy * 16 + jj * 2);
        #pragma unroll
        for (int i = 0; i < 4; i++) acc[i][jj] = add2(acc[i][jj], bp);
    }
}

// At[n][m] = elu(a[m][n]) for this thread's 4x16 tile, conflict-free float4 STS
__device__ __forceinline__ void write_elu(float* __restrict__ At,
                                          const ull a[4][8], int tx, int wy) {
    #pragma unroll
    for (int jj = 0; jj < 8; jj++) {
        float2 f0 = unpack2(a[0][jj]);
        float2 f1 = unpack2(a[1][jj]);
        float2 f2 = unpack2(a[2][jj]);
        float2 f3 = unpack2(a[3][jj]);
        int n0 = wy * 16 + jj * 2;
        float4 lo = make_float4(eluf(f0.x), eluf(f1.x), eluf(f2.x), eluf(f3.x));
        float4 hi = make_float4(eluf(f0.y), eluf(f1.y), eluf(f2.y), eluf(f3.y));
        *reinterpret_cast<float4*>(At + n0 * 128 + tx * 4) = lo;
        *reinterpret_cast<float4*>(At + (n0 + 1) * 128 + tx * 4) = hi;
    }
}

__global__ __launch_bounds__(THREADS, 1)
void acn_coupling_kernel(const float* __restrict__ x,
                         const float* __restrict__ W_in,  const float* __restrict__ b_in,
                         const float* __restrict__ W_b1,  const float* __restrict__ b_b1,
                         const float* __restrict__ W_b2,  const float* __restrict__ b_b2,
                         const float* __restrict__ W_out, const float* __restrict__ b_out,
                         float* __restrict__ y, int nrow) {
    extern __shared__ float sm[];
    float*  At     = sm + OFF_AT;
    float*  Wp     = sm + OFF_WP;
    float2* xs     = reinterpret_cast<float2*>(sm + OFF_XS);   // stride 65 float2/row
    float*  bias_s = sm + OFF_BIAS;
    float*  st_s   = sm;  // overlay (dead At/Wp) after final GEMM

    const int tid = threadIdx.x;
    const int tx  = tid & 31;   // row direction, 4 rows each
    const int wy  = tid >> 5;   // col direction, 16 cols each
    const int r0  = blockIdx.x * ROWS_PER_BLOCK;

    // ---- phase A: stage x (as float2 pairs), biases, layer-1 weights -------
    const float2* x2 = reinterpret_cast<const float2*>(x);
    #pragma unroll 1
    for (int u = tid; u < ROWS_PER_BLOCK * P; u += THREADS) {
        int r = u >> 6, j = u & 63;
        float2 v = make_float2(0.0f, 0.0f);
        if (r0 + r < nrow) v = x2[(size_t)(r0 + r) * P + j];
        xs[r * 65 + j] = v;
    }
    #pragma unroll 1
    for (int u = tid; u < 4 * H; u += THREADS) {
        int l = u >> 7, idx = u & 127;
        const float* b = (l == 0) ? b_in : (l == 1) ? b_b1 : (l == 2) ? b_b2 : b_out;
        bias_s[u] = b[idx];
    }
    load_wp<64>(Wp, W_in, tid);
    __syncthreads();

    // ---- phase B: At[k][m] = x_pass[m][k]  (transpose via shared) ----------
    #pragma unroll 1
    for (int u = tid; u < P * ROWS_PER_BLOCK; u += THREADS) {
        int m = u & 127, c = u >> 7;
        At[c * 128 + m] = xs[m * 65 + c].x;
    }
    __syncthreads();

    ull acc[4][8], res[4][8];

    // ---- layer 1: a1 = x_pass @ W_in^T + b_in ; res = a1 -------------------
    gemm<64>(At, Wp, acc, tx, wy);
    apply_bias(acc, bias_s + 0, wy);
    #pragma unroll
    for (int i = 0; i < 4; i++)
        #pragma unroll
        for (int jj = 0; jj < 8; jj++) res[i][jj] = acc[i][jj];
    __syncthreads();
    write_elu(At, acc, tx, wy);
    load_wp<128>(Wp, W_b1, tid);
    __syncthreads();

    // ---- layer 2: a2 = elu(a1) @ W_b1^T + b_b1 ; res += a2 -----------------
    gemm<128>(At, Wp, acc, tx, wy);
    apply_bias(acc, bias_s + 128, wy);
    #pragma unroll
    for (int i = 0; i < 4; i++)
        #pragma unroll
        for (int jj = 0; jj < 8; jj++) res[i][jj] = add2(res[i][jj], acc[i][jj]);
    __syncthreads();
    write_elu(At, acc, tx, wy);
    load_wp<128>(Wp, W_b2, tid);
    __syncthreads();

    // ---- layer 3: a3 = elu(a2) @ W_b2^T + b_b2 ; res += a3 -----------------
    gemm<128>(At, Wp, acc, tx, wy);
    apply_bias(acc, bias_s + 256, wy);
    #pragma unroll
    for (int i = 0; i < 4; i++)
        #pragma unroll
        for (int jj = 0; jj < 8; jj++) res[i][jj] = add2(res[i][jj], acc[i][jj]);
    __syncthreads();
    write_elu(At, res, tx, wy);          // input to final layer is elu(res)
    load_wp<128>(Wp, W_out, tid);
    __syncthreads();

    // ---- layer 4: st = elu(res) @ W_out^T + b_out --------------------------
    gemm<128>(At, Wp, acc, tx, wy);
    apply_bias(acc, bias_s + 384, wy);
    __syncthreads();   // everyone done reading At/Wp -> safe to overlay st_s

    // st_s[n][m], stride 129 (conflict-free epilogue reads)
    #pragma unroll
    for (int jj = 0; jj < 8; jj++) {
        int n0 = wy * 16 + jj * 2;
        #pragma unroll
        for (int i = 0; i < 4; i++) {
            float2 f = unpack2(acc[i][jj]);
            int m = tx * 4 + i;
            st_s[n0 * 129 + m]       = f.x;
            st_s[(n0 + 1) * 129 + m] = f.y;
        }
    }
    __syncthreads();

    // ---- epilogue: y[2j] = x_pass ; y[2j+1] = x_trans*exp(2*tanh(s)) + t ---
    float2* y2 = reinterpret_cast<float2*>(y);
    #pragma unroll 1
    for (int u = tid; u < ROWS_PER_BLOCK * P; u += THREADS) {
        int j = u & 63, r = u >> 6;
        if (r0 + r >= nrow) continue;
        float2 xv = xs[r * 65 + j];
        float s_raw = st_s[j * 129 + r];
        float t     = st_s[(j + 64) * 129 + r];
        float s = 2.0f * tanhf(s_raw);   // accurate tanh: s feeds exp, keep error ~1e-7
        float2 o;
        o.x = xv.x;
        o.y = xv.y * __expf(s) + t;      // __expf rel err ~2^-21, well under gate
        y2[(size_t)(r0 + r) * P + j] = o;
    }
}

extern "C" void kernel_launch(void* const* d_in, const int* in_sizes, int n_in,
                              void* d_out, int out_size) {
    const float* x     = (const float*)d_in[0];
    const float* W_in  = (const float*)d_in[1];
    const float* b_in  = (const float*)d_in[2];
    const float* W_b1  = (const float*)d_in[3];
    const float* b_b1  = (const float*)d_in[4];
    const float* W_b2  = (const float*)d_in[5];
    const float* b_b2  = (const float*)d_in[6];
    const float* W_out = (const float*)d_in[7];
    const float* b_out = (const float*)d_in[8];
    float* y = (float*)d_out;

    int nrow = in_sizes[0] / 128;
    int grid = (nrow + ROWS_PER_BLOCK - 1) / ROWS_PER_BLOCK;
    size_t smem = SMEM_FLOATS * sizeof(float);

    cudaFuncSetAttribute(acn_coupling_kernel,
                         cudaFuncAttributeMaxDynamicSharedMemorySize, (int)smem);
    acn_coupling_kernel<<<grid, THREADS, smem>>>(
        x, W_in, b_in, W_b1, b_b1, W_b2, b_b2, W_out, b_out, y, nrow);
}

// round 11
// speedup vs baseline: 1.3725x; 1.3725x over previous
#include <cuda_runtime.h>
#include <cstdint>

// ---------------------------------------------------------------------------
// Affine coupling layer, fp32, packed-f32x2 register-tiled GEMM chain.
// R11 (= R3 resubmit; broker timeouts R3-R10): 512 threads/block (4 warps per
// SMSP for latency hiding), per-thread tile 4 rows x 8 cols,
// software-pipelined double-buffered k-loop.
// ---------------------------------------------------------------------------

typedef unsigned long long ull;

__device__ __forceinline__ ull pack2(float lo, float hi) {
    ull r;
    asm("mov.b64 %0, {%1, %2};" : "=l"(r) : "f"(lo), "f"(hi));
    return r;
}
__device__ __forceinline__ float2 unpack2(ull v) {
    float2 f;
    asm("mov.b64 {%0, %1}, %2;" : "=f"(f.x), "=f"(f.y) : "l"(v));
    return f;
}
__device__ __forceinline__ ull fma2(ull a, ull b, ull c) {
    ull d;
    asm("fma.rn.f32x2 %0, %1, %2, %3;" : "=l"(d) : "l"(a), "l"(b), "l"(c));
    return d;
}
__device__ __forceinline__ ull add2(ull a, ull b) {
    ull d;
    asm("add.rn.f32x2 %0, %1, %2;" : "=l"(d) : "l"(a), "l"(b));
    return d;
}

// jax.nn.elu alpha=1: x>0 ? x : expm1(x). __expf-1 abs err <=1e-7 (x<0 branch).
__device__ __forceinline__ float eluf(float v) {
    return v > 0.0f ? v : (__expf(v) - 1.0f);
}

static constexpr int ROWS_PER_BLOCK = 128;
static constexpr int THREADS = 512;      // 16 warps, 4 per SMSP
static constexpr int H = 128;
static constexpr int P = 64;

// Shared layout (floats)
static constexpr int OFF_AT   = 0;                   // 16384
static constexpr int OFF_WP   = 16384;               // 16384
static constexpr int OFF_XS   = 32768;               // 128 * 65 float2 = 16640 floats
static constexpr int OFF_BIAS = 32768 + 16640;       // 512
static constexpr int SMEM_FLOATS = OFF_BIAS + 512;   // 49920 floats = 199680 B
// st_s overlays [0, 128*129) after last GEMM (At + head of Wp, both dead).

// W (128 x K row-major) -> paired layout Wp[(n/2)*K + k] = {W[n][k], W[n+1][k]}
template <int K>
__device__ __forceinline__ void load_wp(float* __restrict__ Wp,
                                        const float* __restrict__ W, int tid) {
    #pragma unroll 1
    for (int u = tid; u < 128 * K; u += THREADS) {
        int n = u / K;
        int k = u - n * K;
        Wp[(((n >> 1) * K + k) << 1) + (n & 1)] = __ldg(&W[u]);
    }
}

// acc[m_local][n_pair] += At[k][m] * W[n][k]  over k, double-buffered.
// Thread covers rows tx*4..tx*4+3, col-pairs wy*4..wy*4+3 (cols wy*8..wy*8+7).
template <int K>
__device__ __forceinline__ void gemm(const float* __restrict__ At,
                                     const float* __restrict__ Wp,
                                     ull acc[4][4], int tx, int wy) {
    #pragma unroll
    for (int i = 0; i < 4; i++)
        #pragma unroll
        for (int j = 0; j < 4; j++) acc[i][j] = 0ull;

    const float* wbase = Wp + (wy * 4) * K * 2;   // first col-pair row
    const float* abase = At + tx * 4;

    float4 av[2];
    ull w[2][4];

    av[0] = *reinterpret_cast<const float4*>(abase);
    #pragma unroll
    for (int j = 0; j < 4; j++)
        w[0][j] = *reinterpret_cast<const ull*>(wbase + (j * K) * 2);

    #pragma unroll 2
    for (int k = 0; k < K; k++) {
        const int cur = k & 1, nxt = cur ^ 1;
        if (k + 1 < K) {
            av[nxt] = *reinterpret_cast<const float4*>(abase + (k + 1) * 128);
            #pragma unroll
            for (int j = 0; j < 4; j++)
                w[nxt][j] = *reinterpret_cast<const ull*>(wbase + (j * K + k + 1) * 2);
        }
        float a[4] = {av[cur].x, av[cur].y, av[cur].z, av[cur].w};
        #pragma unroll
        for (int i = 0; i < 4; i++) {
            ull ad = pack2(a[i], a[i]);
            #pragma unroll
            for (int j = 0; j < 4; j++)
                acc[i][j] = fma2(ad, w[cur][j], acc[i][j]);
        }
    }
}

__device__ __forceinline__ void apply_bias(ull acc[4][4],
                                           const float* __restrict__ bias_n,
                                           int wy) {
    #pragma unroll
    for (int j = 0; j < 4; j++) {
        ull bp = *reinterpret_cast<const ull*>(bias_n + wy * 8 + j * 2);
        #pragma unroll
        for (int i = 0; i < 4; i++) acc[i][j] = add2(acc[i][j], bp);
    }
}

// At[n][m] = elu(a[m][n]) for this thread's 4x8 tile (float4 STS, conflict-free)
__device__ __forceinline__ void write_elu(float* __restrict__ At,
                                          const ull a[4][4], int tx, int wy) {
    #pragma unroll
    for (int j = 0; j < 4; j++) {
        float2 f0 = unpack2(a[0][j]);
        float2 f1 = unpack2(a[1][j]);
        float2 f2 = unpack2(a[2][j]);
        float2 f3 = unpack2(a[3][j]);
        int n0 = wy * 8 + j * 2;
        float4 lo = make_float4(eluf(f0.x), eluf(f1.x), eluf(f2.x), eluf(f3.x));
        float4 hi = make_float4(eluf(f0.y), eluf(f1.y), eluf(f2.y), eluf(f3.y));
        *reinterpret_cast<float4*>(At + n0 * 128 + tx * 4) = lo;
        *reinterpret_cast<float4*>(At + (n0 + 1) * 128 + tx * 4) = hi;
    }
}

__global__ __launch_bounds__(THREADS, 1)
void acn_coupling_kernel(const float* __restrict__ x,
                         const float* __restrict__ W_in,  const float* __restrict__ b_in,
                         const float* __restrict__ W_b1,  const float* __restrict__ b_b1,
                         const float* __restrict__ W_b2,  const float* __restrict__ b_b2,
                         const float* __restrict__ W_out, const float* __restrict__ b_out,
                         float* __restrict__ y, int nrow) {
    extern __shared__ float sm[];
    float*  At     = sm + OFF_AT;
    float*  Wp     = sm + OFF_WP;
    float2* xs     = reinterpret_cast<float2*>(sm + OFF_XS);   // stride 65 float2
    float*  bias_s = sm + OFF_BIAS;
    float*  st_s   = sm;  // overlay after final GEMM

    const int tid = threadIdx.x;
    const int tx  = tid & 31;   // 4 rows each
    const int wy  = tid >> 5;   // 16 warps x 8 cols = 128 cols
    const int r0  = blockIdx.x * ROWS_PER_BLOCK;

    // ---- phase A: stage x, biases, layer-1 weights --------------------------
    const float2* x2 = reinterpret_cast<const float2*>(x);
    #pragma unroll 1
    for (int u = tid; u < ROWS_PER_BLOCK * P; u += THREADS) {
        int r = u >> 6, j = u & 63;
        float2 v = make_float2(0.0f, 0.0f);
        if (r0 + r < nrow) v = x2[(size_t)(r0 + r) * P + j];
        xs[r * 65 + j] = v;
    }
    {
        int u = tid;  // 4*H == 512 == THREADS
        int l = u >> 7, idx = u & 127;
        const float* b = (l == 0) ? b_in : (l == 1) ? b_b1 : (l == 2) ? b_b2 : b_out;
        bias_s[u] = b[idx];
    }
    load_wp<64>(Wp, W_in, tid);
    __syncthreads();

    // ---- phase B: At[k][m] = x_pass[m][k] -----------------------------------
    #pragma unroll 1
    for (int u = tid; u < P * ROWS_PER_BLOCK; u += THREADS) {
        int m = u & 127, c = u >> 7;
        At[c * 128 + m] = xs[m * 65 + c].x;
    }
    __syncthreads();

    ull acc[4][4], res[4][4];

    // ---- layer 1: a1 = x_pass @ W_in^T + b_in ; res = a1 --------------------
    gemm<64>(At, Wp, acc, tx, wy);
    apply_bias(acc, bias_s + 0, wy);
    #pragma unroll
    for (int i = 0; i < 4; i++)
        #pragma unroll
        for (int j = 0; j < 4; j++) res[i][j] = acc[i][j];
    __syncthreads();
    write_elu(At, acc, tx, wy);
    load_wp<128>(Wp, W_b1, tid);
    __syncthreads();

    // ---- layer 2 ------------------------------------------------------------
    gemm<128>(At, Wp, acc, tx, wy);
    apply_bias(acc, bias_s + 128, wy);
    #pragma unroll
    for (int i = 0; i < 4; i++)
        #pragma unroll
        for (int j = 0; j < 4; j++) res[i][j] = add2(res[i][j], acc[i][j]);
    __syncthreads();
    write_elu(At, acc, tx, wy);
    load_wp<128>(Wp, W_b2, tid);
    __syncthreads();

    // ---- layer 3 ------------------------------------------------------------
    gemm<128>(At, Wp, acc, tx, wy);
    apply_bias(acc, bias_s + 256, wy);
    #pragma unroll
    for (int i = 0; i < 4; i++)
        #pragma unroll
        for (int j = 0; j < 4; j++) res[i][j] = add2(res[i][j], acc[i][j]);
    __syncthreads();
    write_elu(At, res, tx, wy);          // final layer input = elu(res)
    load_wp<128>(Wp, W_out, tid);
    __syncthreads();

    // ---- layer 4: st = elu(res) @ W_out^T + b_out ---------------------------
    gemm<128>(At, Wp, acc, tx, wy);
    apply_bias(acc, bias_s + 384, wy);
    __syncthreads();   // safe to overlay st_s

    // st_s[n][m], stride 129
    #pragma unroll
    for (int j = 0; j < 4; j++) {
        int n0 = wy * 8 + j * 2;
        #pragma unroll
        for (int i = 0; i < 4; i++) {
            float2 f = unpack2(acc[i][j]);
            int m = tx * 4 + i;
            st_s[n0 * 129 + m]       = f.x;
            st_s[(n0 + 1) * 129 + m] = f.y;
        }
    }
    __syncthreads();

    // ---- epilogue: y[2j] = x_pass ; y[2j+1] = x_trans*exp(2 tanh s) + t -----
    float2* y2 = reinterpret_cast<float2*>(y);
    #pragma unroll 1
    for (int u = tid; u < ROWS_PER_BLOCK * P; u += THREADS) {
        int j = u & 63, r = u >> 6;
        if (r0 + r >= nrow) continue;
        float2 xv = xs[r * 65 + j];
        float s_raw = st_s[j * 129 + r];
        float t     = st_s[(j + 64) * 129 + r];
        float s = 2.0f * tanhf(s_raw);
        float2 o;
        o.x = xv.x;
        o.y = xv.y * __expf(s) + t;
        y2[(size_t)(r0 + r) * P + j] = o;
    }
}

extern "C" void kernel_launch(void* const* d_in, const int* in_sizes, int n_in,
                              void* d_out, int out_size) {
    const float* x     = (const float*)d_in[0];
    const float* W_in  = (const float*)d_in[1];
    const float* b_in  = (const float*)d_in[2];
    const float* W_b1  = (const float*)d_in[3];
    const float* b_b1  = (const float*)d_in[4];
    const float* W_b2  = (const float*)d_in[5];
    const float* b_b2  = (const float*)d_in[6];
    const float* W_out = (const float*)d_in[7];
    const float* b_out = (const float*)d_in[8];
    float* y = (float*)d_out;

    int nrow = in_sizes[0] / 128;
    int grid = (nrow + ROWS_PER_BLOCK - 1) / ROWS_PER_BLOCK;
    size_t smem = SMEM_FLOATS * sizeof(float);

    cudaFuncSetAttribute(acn_coupling_kernel,
                         cudaFuncAttributeMaxDynamicSharedMemorySize, (int)smem);
    acn_coupling_kernel<<<grid, THREADS, smem>>>(
        x, W_in, b_in, W_b1, b_b1, W_b2, b_b2, W_out, b_out, y, nrow);
}

// round 12
// speedup vs baseline: 1.8459x; 1.3449x over previous
#include <cuda_runtime.h>
#include <cstdint>

// ---------------------------------------------------------------------------
// Affine coupling layer, fp32 f32x2 GEMM chain. R12:
//  - prep kernel pre-pairs weights into __device__ global (cp.async-friendly)
//  - main kernel: cp.async double-buffered weights (P0/P1), zero exposed
//    GMEM weight loads
//  - W read as LDS.128 (2 k's per load) -> crossbar 96 cyc/SM/k < 128 FMA floor
//  - xs staging dropped; x re-read at epilogue
// ---------------------------------------------------------------------------

typedef unsigned long long ull;

__device__ float g_wp[4 * 16384];   // paired weights: [layer][(n/2)*2K + 2k + (n&1)]

__device__ __forceinline__ ull pack2(float lo, float hi) {
    ull r;
    asm("mov.b64 %0, {%1, %2};" : "=l"(r) : "f"(lo), "f"(hi));
    return r;
}
__device__ __forceinline__ float2 unpack2(ull v) {
    float2 f;
    asm("mov.b64 {%0, %1}, %2;" : "=f"(f.x), "=f"(f.y) : "l"(v));
    return f;
}
__device__ __forceinline__ ull fma2(ull a, ull b, ull c) {
    ull d;
    asm("fma.rn.f32x2 %0, %1, %2, %3;" : "=l"(d) : "l"(a), "l"(b), "l"(c));
    return d;
}
__device__ __forceinline__ ull add2(ull a, ull b) {
    ull d;
    asm("add.rn.f32x2 %0, %1, %2;" : "=l"(d) : "l"(a), "l"(b));
    return d;
}
__device__ __forceinline__ float eluf(float v) {
    return v > 0.0f ? v : (__expf(v) - 1.0f);
}

__device__ __forceinline__ void cp_async16(uint32_t dst, const float4* src) {
    asm volatile("cp.async.cg.shared.global [%0], [%1], 16;" :: "r"(dst), "l"(src));
}
#define CP_COMMIT() asm volatile("cp.async.commit_group;" ::: "memory")
#define CP_WAIT(n)  asm volatile("cp.async.wait_group %0;" :: "n"(n) : "memory")

static constexpr int RPB = 128;      // rows per block
static constexpr int THREADS = 512;  // 16 warps

// shared layout (floats)
static constexpr int OFF_AT   = 0;        // 16384
static constexpr int OFF_P0   = 16384;    // 16384 (paired weights, buf 0)
static constexpr int OFF_P1   = 32768;    // 16384 (buf 1)
static constexpr int OFF_BIAS = 49152;    // 512
static constexpr int SMEM_FLOATS = 49664; // 198656 B
// st_s (128*129=16512) overlays At + first 128 floats of P0 (dead after L3).
// x transpose staging overlays P1 (dead before G1 cp.async).

// ---- prep kernel: pair weights into g_wp --------------------------------
__global__ void prep_pair_kernel(const float* __restrict__ W_in,
                                 const float* __restrict__ W_b1,
                                 const float* __restrict__ W_b2,
                                 const float* __restrict__ W_out) {
    int l = blockIdx.y;
    const float* W = (l == 0) ? W_in : (l == 1) ? W_b1 : (l == 2) ? W_b2 : W_out;
    int K = (l == 0) ? 64 : 128;
    int total = 128 * K;
    for (int u = blockIdx.x * blockDim.x + threadIdx.x; u < total;
         u += gridDim.x * blockDim.x) {
        int n = u / K, k = u - n * K;
        g_wp[l * 16384 + (n >> 1) * (2 * K) + 2 * k + (n & 1)] = W[u];
    }
}

// stage one paired weight matrix into smem via cp.async, one commit group
__device__ __forceinline__ void stage_w(uint32_t dst_u32, const float* src,
                                        int quads, int tid) {
    const float4* s4 = (const float4*)src;
    #pragma unroll 1
    for (int u = tid; u < quads; u += THREADS)
        cp_async16(dst_u32 + u * 16, s4 + u);
    CP_COMMIT();
}

// acc[m_local][n_pair] += At[k][m]*W[n][k]; W via LDS.128 = 2 k's per load
template <int K>
__device__ __forceinline__ void gemm(const float* __restrict__ At,
                                     const float* __restrict__ Wp,
                                     ull acc[4][4], int tx, int wy) {
    #pragma unroll
    for (int i = 0; i < 4; i++)
        #pragma unroll
        for (int j = 0; j < 4; j++) acc[i][j] = 0ull;

    const float* wbase = Wp + (wy * 4) * (2 * K);  // pair stride = 2K floats
    const float* abase = At + tx * 4;

    float4 aA[2], aB[2];
    aA[0] = *reinterpret_cast<const float4*>(abase);
    aB[0] = *reinterpret_cast<const float4*>(abase + 128);

    #pragma unroll 2
    for (int kp = 0; kp < K / 2; kp++) {
        const int cur = kp & 1, nxt = cur ^ 1;
        if (kp + 1 < K / 2) {
            aA[nxt] = *reinterpret_cast<const float4*>(abase + (2 * kp + 2) * 128);
            aB[nxt] = *reinterpret_cast<const float4*>(abase + (2 * kp + 3) * 128);
        }
        ull wq0[4], wq1[4];
        #pragma unroll
        for (int j = 0; j < 4; j++) {
            ulonglong2 wv = *reinterpret_cast<const ulonglong2*>(
                wbase + j * (2 * K) + 4 * kp);
            wq0[j] = wv.x;   // n-pair at k
            wq1[j] = wv.y;   // n-pair at k+1
        }
        float a0v[4] = {aA[cur].x, aA[cur].y, aA[cur].z, aA[cur].w};
        float a1v[4] = {aB[cur].x, aB[cur].y, aB[cur].z, aB[cur].w};
        #pragma unroll
        for (int i = 0; i < 4; i++) {
            ull ad0 = pack2(a0v[i], a0v[i]);
            ull ad1 = pack2(a1v[i], a1v[i]);
            #pragma unroll
            for (int j = 0; j < 4; j++) acc[i][j] = fma2(ad0, wq0[j], acc[i][j]);
            #pragma unroll
            for (int j = 0; j < 4; j++) acc[i][j] = fma2(ad1, wq1[j], acc[i][j]);
        }
    }
}

__device__ __forceinline__ void apply_bias(ull acc[4][4],
                                           const float* __restrict__ bias_n,
                                           int wy) {
    #pragma unroll
    for (int j = 0; j < 4; j++) {
        ull bp = *reinterpret_cast<const ull*>(bias_n + wy * 8 + j * 2);
        #pragma unroll
        for (int i = 0; i < 4; i++) acc[i][j] = add2(acc[i][j], bp);
    }
}

__device__ __forceinline__ void write_elu(float* __restrict__ At,
                                          const ull a[4][4], int tx, int wy) {
    #pragma unroll
    for (int j = 0; j < 4; j++) {
        float2 f0 = unpack2(a[0][j]);
        float2 f1 = unpack2(a[1][j]);
        float2 f2 = unpack2(a[2][j]);
        float2 f3 = unpack2(a[3][j]);
        int n0 = wy * 8 + j * 2;
        float4 lo = make_float4(eluf(f0.x), eluf(f1.x), eluf(f2.x), eluf(f3.x));
        float4 hi = make_float4(eluf(f0.y), eluf(f1.y), eluf(f2.y), eluf(f3.y));
        *reinterpret_cast<float4*>(At + n0 * 128 + tx * 4) = lo;
        *reinterpret_cast<float4*>(At + (n0 + 1) * 128 + tx * 4) = hi;
    }
}

__global__ __launch_bounds__(THREADS, 1)
void acn_coupling_kernel(const float* __restrict__ x,
                         const float* __restrict__ b_in,
                         const float* __restrict__ b_b1,
                         const float* __restrict__ b_b2,
                         const float* __restrict__ b_out,
                         float* __restrict__ y, int nrow) {
    extern __shared__ float sm[];
    float* At     = sm + OFF_AT;
    float* P0     = sm + OFF_P0;
    float* P1     = sm + OFF_P1;
    float* bias_s = sm + OFF_BIAS;
    float* st_s   = sm;   // overlay after final GEMM

    uint32_t sb  = (uint32_t)__cvta_generic_to_shared(sm);
    uint32_t P0a = sb + OFF_P0 * 4;
    uint32_t P1a = sb + OFF_P1 * 4;

    const int tid = threadIdx.x;
    const int tx  = tid & 31;
    const int wy  = tid >> 5;
    const int r0  = blockIdx.x * RPB;

    // G0: layer-1 weights -> P0 (K=64 paired = 8192 floats = 2048 quads)
    stage_w(P0a, g_wp + 0, 2048, tid);

    // biases (4*128 == THREADS)
    {
        int l = tid >> 7, idx = tid & 127;
        const float* b = (l == 0) ? b_in : (l == 1) ? b_b1 : (l == 2) ? b_b2 : b_out;
        bias_s[tid] = b[idx];
    }

    // x_pass staging into P1 area (stride-65 for conflict-free transpose)
    const float2* x2 = reinterpret_cast<const float2*>(x);
    #pragma unroll 1
    for (int u = tid; u < RPB * 64; u += THREADS) {
        int r = u >> 6, j = u & 63;
        float v = 0.0f;
        if (r0 + r < nrow) v = x2[(size_t)(r0 + r) * 64 + j].x;
        P1[r * 65 + j] = v;
    }
    __syncthreads();

    // transpose: At[c][m] = x_pass[m][c]
    #pragma unroll 1
    for (int u = tid; u < 64 * 128; u += THREADS) {
        int m = u & 127, c = u >> 7;
        At[c * 128 + m] = P1[m * 65 + c];
    }
    __syncthreads();   // P1 now free

    // G1: layer-2 weights -> P1
    stage_w(P1a, g_wp + 16384, 4096, tid);
    CP_WAIT(1);        // G0 complete
    __syncthreads();

    ull acc[4][4], res[4][4];

    // ---- layer 1 (P0, K=64) ------------------------------------------------
    gemm<64>(At, P0, acc, tx, wy);
    apply_bias(acc, bias_s + 0, wy);
    #pragma unroll
    for (int i = 0; i < 4; i++)
        #pragma unroll
        for (int j = 0; j < 4; j++) res[i][j] = acc[i][j];
    __syncthreads();                       // all gemm reads of P0/At done
    stage_w(P0a, g_wp + 2 * 16384, 4096, tid);   // G2: layer-3 -> P0
    CP_WAIT(1);                            // G1 complete
    write_elu(At, acc, tx, wy);
    __syncthreads();

    // ---- layer 2 (P1) ------------------------------------------------------
    gemm<128>(At, P1, acc, tx, wy);
    apply_bias(acc, bias_s + 128, wy);
    #pragma unroll
    for (int i = 0; i < 4; i++)
        #pragma unroll
        for (int j = 0; j < 4; j++) res[i][j] = add2(res[i][j], acc[i][j]);
    __syncthreads();
    stage_w(P1a, g_wp + 3 * 16384, 4096, tid);   // G3: layer-4 -> P1
    CP_WAIT(1);                            // G2 complete
    write_elu(At, acc, tx, wy);
    __syncthreads();

    // ---- layer 3 (P0) ------------------------------------------------------
    gemm<128>(At, P0, acc, tx, wy);
    apply_bias(acc, bias_s + 256, wy);
    #pragma unroll
    for (int i = 0; i < 4; i++)
        #pragma unroll
        for (int j = 0; j < 4; j++) res[i][j] = add2(res[i][j], acc[i][j]);
    __syncthreads();
    CP_WAIT(0);                            // G3 complete
    write_elu(At, res, tx, wy);            // final layer input = elu(res)
    __syncthreads();

    // ---- layer 4 (P1): st = elu(res) @ W_out^T + b_out ---------------------
    gemm<128>(At, P1, acc, tx, wy);
    apply_bias(acc, bias_s + 384, wy);
    __syncthreads();   // safe to overlay st_s (At + P0 head, both dead)

    #pragma unroll
    for (int j = 0; j < 4; j++) {
        int n0 = wy * 8 + j * 2;
        #pragma unroll
        for (int i = 0; i < 4; i++) {
            float2 f = unpack2(acc[i][j]);
            int m = tx * 4 + i;
            st_s[n0 * 129 + m]       = f.x;
            st_s[(n0 + 1) * 129 + m] = f.y;
        }
    }
    __syncthreads();

    // ---- epilogue: re-read x; y = [x_pass, x_trans*exp(2 tanh s) + t] ------
    float2* y2 = reinterpret_cast<float2*>(y);
    #pragma unroll 1
    for (int u = tid; u < RPB * 64; u += THREADS) {
        int j = u & 63, r = u >> 6;
        if (r0 + r >= nrow) continue;
        float2 xv = x2[(size_t)(r0 + r) * 64 + j];
        float s_raw = st_s[j * 129 + r];
        float t     = st_s[(j + 64) * 129 + r];
        float s = 2.0f * tanhf(s_raw);
        float2 o;
        o.x = xv.x;
        o.y = xv.y * __expf(s) + t;
        y2[(size_t)(r0 + r) * 64 + j] = o;
    }
}

extern "C" void kernel_launch(void* const* d_in, const int* in_sizes, int n_in,
                              void* d_out, int out_size) {
    const float* x     = (const float*)d_in[0];
    const float* W_in  = (const float*)d_in[1];
    const float* b_in  = (const float*)d_in[2];
    const float* W_b1  = (const float*)d_in[3];
    const float* b_b1  = (const float*)d_in[4];
    const float* W_b2  = (const float*)d_in[5];
    const float* b_b2  = (const float*)d_in[6];
    const float* W_out = (const float*)d_in[7];
    const float* b_out = (const float*)d_in[8];
    float* y = (float*)d_out;

    int nrow = in_sizes[0] / 128;
    int grid = (nrow + RPB - 1) / RPB;
    size_t smem = SMEM_FLOATS * sizeof(float);

    prep_pair_kernel<<<dim3(16, 4), 256>>>(W_in, W_b1, W_b2, W_out);

    cudaFuncSetAttribute(acn_coupling_kernel,
                         cudaFuncAttributeMaxDynamicSharedMemorySize, (int)smem);
    acn_coupling_kernel<<<grid, THREADS, smem>>>(
        x, b_in, b_b1, b_b2, b_out, y, nrow);
}

// round 16
// speedup vs baseline: 3.3881x; 1.8355x over previous
#include <cuda_runtime.h>
#include <cuda_bf16.h>
#include <cstdint>

// ---------------------------------------------------------------------------
// R16 (= R15 resubmit; broker timeout): split-bf16 (3-term) GEMM chain via
// ldmatrix + mma.sync (m16n8k16 bf16, fp32 accum) — family-safe on sm_103.
//   D = A_hi*W_hi + A_hi*W_lo + A_lo*W_hi
// prep kernel pre-splits weights into padded bf16 planes in global; main
// kernel cp.asyncs them double-buffered (R12 scheme). Activations split to
// bf16 hi/lo smem planes each layer; residual lives in mma C fragments.
// ---------------------------------------------------------------------------

static constexpr int AST   = 136;               // bf16 elems per padded row
static constexpr int PLANE = 128 * AST * 2;     // 34816 B per plane
__device__ __align__(16) unsigned char g_wimg[4 * 2 * 34816];  // [layer][hi|lo]

// ---- smem layout (bytes) ----
static constexpr int SM_BIAS = 0;                    // 2048
static constexpr int SM_AHI  = 2048;
static constexpr int SM_ALO  = SM_AHI + PLANE;       // 36864
static constexpr int SM_W0   = SM_ALO + PLANE;       // 71680 (hi, lo consecutive)
static constexpr int SM_W1   = SM_W0 + 2 * PLANE;    // 141312
static constexpr int SMEM_BYTES = SM_W1 + 2 * PLANE; // 210944
// st_s (128*129*4 = 66048 B) overlays A planes after layer 4.

static constexpr int THREADS = 512;   // 16 warps

__device__ __forceinline__ float eluf(float v) {
    return v > 0.0f ? v : (__expf(v) - 1.0f);
}

// split fp32 pair -> packed bf16 hi / lo words
__device__ __forceinline__ uint32_t pack_hl(float v0, float v1, uint32_t& lopack) {
    __nv_bfloat16 h0 = __float2bfloat16(v0);
    __nv_bfloat16 h1 = __float2bfloat16(v1);
    __nv_bfloat16 l0 = __float2bfloat16(v0 - __bfloat162float(h0));
    __nv_bfloat16 l1 = __float2bfloat16(v1 - __bfloat162float(h1));
    lopack = (uint32_t)__bfloat16_as_ushort(l0) | ((uint32_t)__bfloat16_as_ushort(l1) << 16);
    return  (uint32_t)__bfloat16_as_ushort(h0) | ((uint32_t)__bfloat16_as_ushort(h1) << 16);
}

__device__ __forceinline__ void ldsm4(uint32_t* r, uint32_t addr) {
    asm volatile("ldmatrix.sync.aligned.m8n8.x4.shared.b16 {%0,%1,%2,%3}, [%4];"
                 : "=r"(r[0]), "=r"(r[1]), "=r"(r[2]), "=r"(r[3]) : "r"(addr));
}
__device__ __forceinline__ void mma_bf16(float* c, const uint32_t* a,
                                         uint32_t b0, uint32_t b1) {
    asm volatile("mma.sync.aligned.m16n8k16.row.col.f32.bf16.bf16.f32 "
                 "{%0,%1,%2,%3}, {%4,%5,%6,%7}, {%8,%9}, {%0,%1,%2,%3};"
                 : "+f"(c[0]), "+f"(c[1]), "+f"(c[2]), "+f"(c[3])
                 : "r"(a[0]), "r"(a[1]), "r"(a[2]), "r"(a[3]), "r"(b0), "r"(b1));
}

__device__ __forceinline__ void cp_async16(uint32_t dst, const void* src) {
    asm volatile("cp.async.cg.shared.global [%0], [%1], 16;" :: "r"(dst), "l"(src));
}
#define CP_COMMIT() asm volatile("cp.async.commit_group;" ::: "memory")
#define CP_WAIT(n)  asm volatile("cp.async.wait_group %0;" :: "n"(n) : "memory")

__device__ __forceinline__ void stage(uint32_t dst, const unsigned char* src, int tid) {
    #pragma unroll 1
    for (int u = tid; u < 2 * PLANE / 16; u += THREADS)   // 4352 quads
        cp_async16(dst + u * 16, src + u * 16);
    CP_COMMIT();
}

// ---- prep kernel: split weights into padded bf16 planes -----------------
__global__ void prep_kernel(const float* __restrict__ W_in,
                            const float* __restrict__ W_b1,
                            const float* __restrict__ W_b2,
                            const float* __restrict__ W_out) {
    int l = blockIdx.y;
    const float* W = (l == 0) ? W_in : (l == 1) ? W_b1 : (l == 2) ? W_b2 : W_out;
    int K = (l == 0) ? 64 : 128;
    __nv_bfloat16* hi = (__nv_bfloat16*)(g_wimg + l * 2 * PLANE);
    __nv_bfloat16* lo = (__nv_bfloat16*)(g_wimg + l * 2 * PLANE + PLANE);
    int total = 128 * K;
    for (int u = blockIdx.x * blockDim.x + threadIdx.x; u < total;
         u += gridDim.x * blockDim.x) {
        int n = u / K, k = u - n * K;
        float v = W[u];
        __nv_bfloat16 h = __float2bfloat16(v);
        hi[n * AST + k] = h;
        lo[n * AST + k] = __float2bfloat16(v - __bfloat162float(h));
    }
}

// gemm: acc[tile][4] += A(128xK) * W(128xK)^T for this warp's 16x64 patch
template <int K>
__device__ __forceinline__ void gemm_mma(uint32_t sb, uint32_t wbase,
                                         float acc[8][4], int wid, int lane) {
    const int mbase = (wid & 7) * 16;
    const int nbase = (wid >> 3) * 64;
    const uint32_t aHi = sb + SM_AHI, aLo = sb + SM_ALO;
    const uint32_t wHi = wbase, wLo = wbase + PLANE;

    #pragma unroll
    for (int t = 0; t < 8; t++)
        #pragma unroll
        for (int j = 0; j < 4; j++) acc[t][j] = 0.0f;

    // A x4 lane address: lanes 0-15 rows 0-15 @kLo, 16-31 rows 0-15 @kHi
    const uint32_t aoffL = (uint32_t)((mbase + (lane & 15)) * AST + (lane >> 4) * 8) * 2;
    // B x4 lane address: {0-7: n kLo, 8-15: n kHi, 16-23: n+8 kLo, 24-31: n+8 kHi}
    const int bn = ((lane >> 4) << 3) + (lane & 7);
    const int bk = ((lane >> 3) & 1) << 3;

    #pragma unroll
    for (int kc = 0; kc < K / 16; kc++) {
        uint32_t ah[4], al[4];
        ldsm4(ah, aHi + aoffL + kc * 32);
        ldsm4(al, aLo + aoffL + kc * 32);
        #pragma unroll
        for (int p = 0; p < 4; p++) {
            uint32_t boff = (uint32_t)((nbase + p * 16 + bn) * AST + kc * 16 + bk) * 2;
            uint32_t bh[4], bl[4];
            ldsm4(bh, wHi + boff);
            ldsm4(bl, wLo + boff);
            mma_bf16(acc[p * 2],     ah, bh[0], bh[1]);
            mma_bf16(acc[p * 2],     ah, bl[0], bl[1]);
            mma_bf16(acc[p * 2],     al, bh[0], bh[1]);
            mma_bf16(acc[p * 2 + 1], ah, bh[2], bh[3]);
            mma_bf16(acc[p * 2 + 1], ah, bl[2], bl[3]);
            mma_bf16(acc[p * 2 + 1], al, bh[2], bh[3]);
        }
    }
}

// epilogue: bias + residual + elu + split -> A planes (next layer input)
template <int LAYER>   // 0,1,2
__device__ __forceinline__ void epi(float acc[8][4], float* res,
                                    const float* bias_s, char* smc,
                                    int wid, int lane) {
    const int mbase = (wid & 7) * 16;
    const int nbase = (wid >> 3) * 64;
    const int m0 = mbase + (lane >> 2);
    #pragma unroll
    for (int t = 0; t < 8; t++) {
        int n0 = nbase + t * 8 + 2 * (lane & 3);
        float b0 = bias_s[LAYER * 128 + n0];
        float b1 = bias_s[LAYER * 128 + n0 + 1];
        float v0 = acc[t][0] + b0, v1 = acc[t][1] + b1;
        float v2 = acc[t][2] + b0, v3 = acc[t][3] + b1;
        if (LAYER == 0) {
            res[t * 4 + 0] = v0; res[t * 4 + 1] = v1;
            res[t * 4 + 2] = v2; res[t * 4 + 3] = v3;
        } else {
            res[t * 4 + 0] += v0; res[t * 4 + 1] += v1;
            res[t * 4 + 2] += v2; res[t * 4 + 3] += v3;
        }
        float e0, e1, e2, e3;
        if (LAYER == 2) {
            e0 = eluf(res[t * 4 + 0]); e1 = eluf(res[t * 4 + 1]);
            e2 = eluf(res[t * 4 + 2]); e3 = eluf(res[t * 4 + 3]);
        } else {
            e0 = eluf(v0); e1 = eluf(v1); e2 = eluf(v2); e3 = eluf(v3);
        }
        uint32_t lpA, hpA = pack_hl(e0, e1, lpA);
        uint32_t lpB, hpB = pack_hl(e2, e3, lpB);
        uint32_t offA = (uint32_t)(m0 * AST + n0) * 2;
        uint32_t offB = (uint32_t)((m0 + 8) * AST + n0) * 2;
        *(uint32_t*)(smc + SM_AHI + offA) = hpA;
        *(uint32_t*)(smc + SM_ALO + offA) = lpA;
        *(uint32_t*)(smc + SM_AHI + offB) = hpB;
        *(uint32_t*)(smc + SM_ALO + offB) = lpB;
    }
}

__global__ __launch_bounds__(THREADS, 1)
void acn_mma_kernel(const float* __restrict__ x,
                    const float* __restrict__ b_in,
                    const float* __restrict__ b_b1,
                    const float* __restrict__ b_b2,
                    const float* __restrict__ b_out,
                    float* __restrict__ y, int nrow) {
    extern __shared__ char smc[];
    uint32_t sb = (uint32_t)__cvta_generic_to_shared(smc);
    float* bias_s = (float*)(smc + SM_BIAS);

    const int tid  = threadIdx.x;
    const int wid  = tid >> 5, lane = tid & 31;
    const int r0   = blockIdx.x * 128;

    // G0: L1 weights -> W0
    stage(sb + SM_W0, g_wimg + 0, tid);

    // biases (4*128 == THREADS)
    {
        int l = tid >> 7, idx = tid & 127;
        const float* b = (l == 0) ? b_in : (l == 1) ? b_b1 : (l == 2) ? b_b2 : b_out;
        bias_s[tid] = b[idx];
    }

    // x_pass -> A planes (cols k<64), split bf16 hi/lo
    const float4* x4 = (const float4*)x;
    #pragma unroll 1
    for (int u = tid; u < 128 * 32; u += THREADS) {
        int r = u >> 5, jp = u & 31;                 // pass features 2jp, 2jp+1
        float4 v = make_float4(0.f, 0.f, 0.f, 0.f);
        if (r0 + r < nrow) v = x4[(size_t)(r0 + r) * 32 + jp];
        uint32_t lp, hp = pack_hl(v.x, v.z, lp);     // even lanes = pass dims
        uint32_t off = (uint32_t)(r * AST + 2 * jp) * 2;
        *(uint32_t*)(smc + SM_AHI + off) = hp;
        *(uint32_t*)(smc + SM_ALO + off) = lp;
    }

    // G1: L2 weights -> W1
    stage(sb + SM_W1, g_wimg + 2 * PLANE, tid);
    CP_WAIT(1);            // G0 done
    __syncthreads();

    float acc[8][4], res[32];

    // ---- layer 1 (K=64, W0) ------------------------------------------------
    gemm_mma<64>(sb, sb + SM_W0, acc, wid, lane);
    __syncthreads();                                  // reads of A/W0 done
    stage(sb + SM_W0, g_wimg + 4 * PLANE, tid);       // G2: L3 -> W0
    epi<0>(acc, res, bias_s, smc, wid, lane);
    CP_WAIT(1);            // G1 done
    __syncthreads();

    // ---- layer 2 (K=128, W1) -----------------------------------------------
    gemm_mma<128>(sb, sb + SM_W1, acc, wid, lane);
    __syncthreads();
    stage(sb + SM_W1, g_wimg + 6 * PLANE, tid);       // G3: L4 -> W1
    epi<1>(acc, res, bias_s, smc, wid, lane);
    CP_WAIT(1);            // G2 done
    __syncthreads();

    // ---- layer 3 (K=128, W0) -----------------------------------------------
    gemm_mma<128>(sb, sb + SM_W0, acc, wid, lane);
    __syncthreads();
    epi<2>(acc, res, bias_s, smc, wid, lane);         // writes elu(res)
    CP_WAIT(0);            // G3 done
    __syncthreads();

    // ---- layer 4 (K=128, W1): st -------------------------------------------
    gemm_mma<128>(sb, sb + SM_W1, acc, wid, lane);
    __syncthreads();       // A planes dead -> safe to overlay st_s
    {
        float* st_s = (float*)(smc + SM_AHI);
        const int mbase = (wid & 7) * 16;
        const int nbase = (wid >> 3) * 64;
        const int m0 = mbase + (lane >> 2);
        #pragma unroll
        for (int t = 0; t < 8; t++) {
            int n0 = nbase + t * 8 + 2 * (lane & 3);
            float b0 = bias_s[384 + n0], b1 = bias_s[384 + n0 + 1];
            st_s[n0 * 129 + m0]           = acc[t][0] + b0;
            st_s[(n0 + 1) * 129 + m0]     = acc[t][1] + b1;
            st_s[n0 * 129 + m0 + 8]       = acc[t][2] + b0;
            st_s[(n0 + 1) * 129 + m0 + 8] = acc[t][3] + b1;
        }
    }
    __syncthreads();

    // ---- output: y = [x_pass, x_trans*exp(2 tanh s) + t] -------------------
    const float2* x2 = (const float2*)x;
    float2* y2 = (float2*)y;
    float* st_s = (float*)(smc + SM_AHI);
    #pragma unroll 1
    for (int u = tid; u < 128 * 64; u += THREADS) {
        int j = u & 63, r = u >> 6;
        if (r0 + r >= nrow) continue;
        float2 xv = x2[(size_t)(r0 + r) * 64 + j];
        float s_raw = st_s[j * 129 + r];
        float t     = st_s[(j + 64) * 129 + r];
        float s = 2.0f * tanhf(s_raw);
        y2[(size_t)(r0 + r) * 64 + j] = make_float2(xv.x, xv.y * __expf(s) + t);
    }
}

extern "C" void kernel_launch(void* const* d_in, const int* in_sizes, int n_in,
                              void* d_out, int out_size) {
    const float* x     = (const float*)d_in[0];
    const float* W_in  = (const float*)d_in[1];
    const float* b_in  = (const float*)d_in[2];
    const float* W_b1  = (const float*)d_in[3];
    const float* b_b1  = (const float*)d_in[4];
    const float* W_b2  = (const float*)d_in[5];
    const float* b_b2  = (const float*)d_in[6];
    const float* W_out = (const float*)d_in[7];
    const float* b_out = (const float*)d_in[8];
    float* y = (float*)d_out;

    int nrow = in_sizes[0] / 128;
    int grid = (nrow + 127) / 128;

    prep_kernel<<<dim3(16, 4), 256>>>(W_in, W_b1, W_b2, W_out);

    cudaFuncSetAttribute(acn_mma_kernel,
                         cudaFuncAttributeMaxDynamicSharedMemorySize, SMEM_BYTES);
    acn_mma_kernel<<<grid, THREADS, SMEM_BYTES>>>(
        x, b_in, b_b1, b_b2, b_out, y, nrow);
}